// round 10
// baseline (speedup 1.0000x reference)
#include <cuda_runtime.h>
#include <math.h>
#include <stdint.h>

#define EMBED 1024
#define NHEAD 16
#define HDIM  64
#define BATCH 2
#define QLEN  2048
#define KLEN  2048
#define MROWS (BATCH*QLEN)   // 4096
#define RU    1024           // u32 per packed row (1 u32 per element)

// ---------------------------------------------------------------------------
// Packed split-bf16: pair p = u32[2p]=bf16x2(hi x0,hi x1), u32[2p+1]=lo pair.
// ---------------------------------------------------------------------------
__device__ uint32_t g_in2[(size_t)3 * MROWS * RU];           // query2,key2,val2
__device__ uint32_t g_W2 [(size_t)4 * EMBED * RU];           // Wq2,Wk2,Wv2,Wo2
__device__ uint32_t g_Qb [(size_t)MROWS * RU];               // packed along d
__device__ uint32_t g_Kb [(size_t)MROWS * RU];               // packed along d
__device__ uint32_t g_Vb [(size_t)BATCH * NHEAD * HDIM * KLEN]; // [b][h][d][key-pairs]
__device__ uint32_t g_Cb [(size_t)MROWS * RU];               // ctx, packed along d
__device__ float    g_pen[(size_t)BATCH * KLEN];

// ---------------------------------------------------------------------------
// helpers
// ---------------------------------------------------------------------------
__device__ __forceinline__ void packsplit(float x0, float x1,
                                          uint32_t& hi, uint32_t& lo) {
    uint32_t h;
    asm("cvt.rn.bf16x2.f32 %0, %1, %2;" : "=r"(h) : "f"(x1), "f"(x0));
    float h0 = __uint_as_float(h << 16);
    float h1 = __uint_as_float(h & 0xffff0000u);
    float l0 = x0 - h0, l1 = x1 - h1;
    uint32_t l;
    asm("cvt.rn.bf16x2.f32 %0, %1, %2;" : "=r"(l) : "f"(l1), "f"(l0));
    hi = h; lo = l;
}

__device__ __forceinline__ void mma16(float* c, const uint32_t* a, const uint32_t* b) {
    asm volatile(
        "mma.sync.aligned.m16n8k16.row.col.f32.bf16.bf16.f32 "
        "{%0,%1,%2,%3}, {%4,%5,%6,%7}, {%8,%9}, {%0,%1,%2,%3};\n"
        : "+f"(c[0]), "+f"(c[1]), "+f"(c[2]), "+f"(c[3])
        : "r"(a[0]), "r"(a[1]), "r"(a[2]), "r"(a[3]), "r"(b[0]), "r"(b[1]));
}

__device__ __forceinline__ void cpa16(uint32_t dst, const void* src) {
    asm volatile("cp.async.cg.shared.global [%0], [%1], 16;\n" :: "r"(dst), "l"(src));
}
__device__ __forceinline__ void cpa_commit() {
    asm volatile("cp.async.commit_group;\n");
}
template <int N>
__device__ __forceinline__ void cpa_wait() {
    asm volatile("cp.async.wait_group %0;\n" :: "n"(N));
}

// ---------------------------------------------------------------------------
// prep: split inputs/weights into packed split-bf16; mask -> penalty floats.
// ---------------------------------------------------------------------------
#define SEG_IN  ((size_t)MROWS * EMBED / 4)
#define SEG_W   ((size_t)EMBED * EMBED / 4)
#define N_IN    (3 * SEG_IN)
#define N_W     (4 * SEG_W)
#define N_MASK  ((size_t)BATCH * KLEN / 4)

__global__ __launch_bounds__(256) void prep_split(
    const float* __restrict__ q,  const float* __restrict__ k,
    const float* __restrict__ v,
    const float* __restrict__ wq, const float* __restrict__ wk,
    const float* __restrict__ wv, const float* __restrict__ wo,
    const int* __restrict__ mask)
{
    const size_t total = N_IN + N_W + N_MASK;
    for (size_t u = (size_t)blockIdx.x * blockDim.x + threadIdx.x; u < total;
         u += (size_t)gridDim.x * blockDim.x) {
        if (u < N_IN) {
            int which = (int)(u / SEG_IN);
            size_t off = u - (size_t)which * SEG_IN;
            const float* src = which == 0 ? q : which == 1 ? k : v;
            float sc = which == 0 ? (1.0f / 32.0f) : 1.0f;
            float4 x = ((const float4*)src)[off];
            uint4 o;
            packsplit(x.x * sc, x.y * sc, o.x, o.y);
            packsplit(x.z * sc, x.w * sc, o.z, o.w);
            ((uint4*)(g_in2 + (size_t)which * MROWS * RU))[off] = o;
        } else if (u < N_IN + N_W) {
            size_t uu = u - N_IN;
            int which = (int)(uu / SEG_W);
            size_t off = uu - (size_t)which * SEG_W;
            const float* src = which == 0 ? wq : which == 1 ? wk
                              : which == 2 ? wv : wo;
            float4 x = ((const float4*)src)[off];
            uint4 o;
            packsplit(x.x, x.y, o.x, o.y);
            packsplit(x.z, x.w, o.z, o.w);
            ((uint4*)(g_W2 + (size_t)which * EMBED * RU))[off] = o;
        } else {
            size_t off = u - N_IN - N_W;
            int4 m = ((const int4*)mask)[off];
            float4 p;
            p.x = m.x ? 10000.0f : 0.0f;
            p.y = m.y ? 10000.0f : 0.0f;
            p.z = m.z ? 10000.0f : 0.0f;
            p.w = m.w ? 10000.0f : 0.0f;
            ((float4*)g_pen)[off] = p;
        }
    }
}

// ---------------------------------------------------------------------------
// GEMM core: 256x128 block tile, 256 thr = 8 warps (4m x 2n), warp 64x64.
// BK=32 elems, 3-stage cp.async pipeline, smem row stride 40 u32, 1 CTA/SM.
// ---------------------------------------------------------------------------
#define RG 40
#define STU (256 * RG + 128 * RG)              // 15360 u32 per stage
#define OFF_B (256 * RG)                       // 10240 u32: B within stage
#define GEMM_SMEM (3 * STU * 4)                // 184320 B
#define GT (EMBED / 32)                        // 32 k-tiles

__device__ __forceinline__ void gemm_load_tile(
    uint32_t sbase, int stage, const uint32_t* __restrict__ A2,
    const uint32_t* __restrict__ W2, int m0, int n0, int t)
{
    const int tid = threadIdx.x;
    const int kof = t * 32;
    const uint32_t st = sbase + (uint32_t)(stage * STU * 4);
#pragma unroll
    for (int it = 0; it < 8; it++) {
        int l = tid + it * 256;                // 0..2047
        int row = l >> 3, c = l & 7;
        cpa16(st + (uint32_t)((row * RG + c * 4) * 4),
              A2 + (size_t)(m0 + row) * RU + kof + c * 4);
    }
#pragma unroll
    for (int it = 0; it < 4; it++) {
        int l = tid + it * 256;                // 0..1023
        int row = l >> 3, c = l & 7;
        cpa16(st + (uint32_t)((OFF_B + row * RG + c * 4) * 4),
              W2 + (size_t)(n0 + row) * RU + kof + c * 4);
    }
}

__device__ __forceinline__ void gemm_core(
    const uint32_t* __restrict__ A2, const uint32_t* __restrict__ W2,
    uint32_t* smu, float acc[4][8][4], int m0, int n0)
{
    const int tid  = threadIdx.x;
    const int lane = tid & 31;
    const int w    = tid >> 5;
    const int g    = lane >> 2;
    const int tk   = lane & 3;
    const int wm   = (w & 3) * 64;             // 4 m-warps
    const int wn   = (w >> 2) * 64;            // 2 n-warps
    uint32_t sbase = (uint32_t)__cvta_generic_to_shared(smu);

#pragma unroll
    for (int mt = 0; mt < 4; mt++)
#pragma unroll
        for (int nt = 0; nt < 8; nt++)
#pragma unroll
            for (int r = 0; r < 4; r++) acc[mt][nt][r] = 0.f;

    gemm_load_tile(sbase, 0, A2, W2, m0, n0, 0); cpa_commit();
    gemm_load_tile(sbase, 1, A2, W2, m0, n0, 1); cpa_commit();

    for (int t = 0; t < GT; t++) {
        const int s = t % 3;
        if (t + 2 < GT) {
            gemm_load_tile(sbase, (t + 2) % 3, A2, W2, m0, n0, t + 2);
            cpa_commit();
            cpa_wait<2>();
        } else if (t + 1 < GT) {
            cpa_wait<1>();
        } else {
            cpa_wait<0>();
        }
        __syncthreads();

        const uint32_t* As = smu + s * STU;
        const uint32_t* Bs = As + OFF_B;
#pragma unroll
        for (int kk = 0; kk < 2; kk++) {
            uint32_t ah[4][4], al[4][4];
            const int cb = kk * 16 + 2 * tk;
#pragma unroll
            for (int mt = 0; mt < 4; mt++) {
                int rb = wm + mt * 16;
                uint2 v;
                v = *(const uint2*)&As[(rb + g) * RG + cb];
                ah[mt][0] = v.x; al[mt][0] = v.y;
                v = *(const uint2*)&As[(rb + g + 8) * RG + cb];
                ah[mt][1] = v.x; al[mt][1] = v.y;
                v = *(const uint2*)&As[(rb + g) * RG + cb + 8];
                ah[mt][2] = v.x; al[mt][2] = v.y;
                v = *(const uint2*)&As[(rb + g + 8) * RG + cb + 8];
                ah[mt][3] = v.x; al[mt][3] = v.y;
            }
#pragma unroll
            for (int nh = 0; nh < 2; nh++) {
                uint32_t bh[4][2], bl[4][2];
#pragma unroll
                for (int j = 0; j < 4; j++) {
                    int nr = wn + (nh * 4 + j) * 8 + g;
                    uint2 b0 = *(const uint2*)&Bs[nr * RG + cb];
                    uint2 b1 = *(const uint2*)&Bs[nr * RG + cb + 8];
                    bh[j][0] = b0.x; bl[j][0] = b0.y;
                    bh[j][1] = b1.x; bl[j][1] = b1.y;
                }
#pragma unroll
                for (int j = 0; j < 4; j++)
#pragma unroll
                    for (int mt = 0; mt < 4; mt++)
                        mma16(acc[mt][nh * 4 + j], ah[mt], bh[j]);
#pragma unroll
                for (int j = 0; j < 4; j++)
#pragma unroll
                    for (int mt = 0; mt < 4; mt++)
                        mma16(acc[mt][nh * 4 + j], al[mt], bh[j]);
#pragma unroll
                for (int j = 0; j < 4; j++)
#pragma unroll
                    for (int mt = 0; mt < 4; mt++)
                        mma16(acc[mt][nh * 4 + j], ah[mt], bl[j]);
            }
        }
        __syncthreads();
    }
}

// QKV projections fused: z = 0 (Q), 1 (K), 2 (V, transposed split output).
__global__ __launch_bounds__(256, 1) void gemm_qkv()
{
    extern __shared__ uint32_t smu[];
    const int z = blockIdx.z;
    const uint32_t* A2 = g_in2 + (size_t)z * MROWS * RU;
    const uint32_t* W2 = g_W2 + (size_t)z * EMBED * RU;
    const int m0 = blockIdx.y * 256;
    const int n0 = blockIdx.x * 128;

    float acc[4][8][4];
    gemm_core(A2, W2, smu, acc, m0, n0);

    const int lane = threadIdx.x & 31;
    const int w    = threadIdx.x >> 5;
    const int g    = lane >> 2;
    const int tk   = lane & 3;
    const int wm   = (w & 3) * 64;
    const int wn   = (w >> 2) * 64;

    if (z < 2) {
        uint32_t* C2 = z == 0 ? g_Qb : g_Kb;
#pragma unroll
        for (int mt = 0; mt < 4; mt++) {
#pragma unroll
            for (int nt = 0; nt < 8; nt++) {
                int m = m0 + wm + mt * 16 + g;
                int n = n0 + wn + nt * 8 + 2 * tk;
                uint2 o;
                packsplit(acc[mt][nt][0], acc[mt][nt][1], o.x, o.y);
                *(uint2*)(C2 + (size_t)m * RU + n) = o;
                packsplit(acc[mt][nt][2], acc[mt][nt][3], o.x, o.y);
                *(uint2*)(C2 + (size_t)(m + 8) * RU + n) = o;
            }
        }
    } else {
        // V: write [b][h][d][key-pairs]; pair keys (g even, g odd) via shfl.
#pragma unroll
        for (int mt = 0; mt < 4; mt++) {
#pragma unroll
            for (int nt = 0; nt < 8; nt++) {
                float c0 = acc[mt][nt][0], c1 = acc[mt][nt][1];
                float c2 = acc[mt][nt][2], c3 = acc[mt][nt][3];
                float oc0 = __shfl_xor_sync(0xFFFFFFFFu, c0, 4);
                float oc1 = __shfl_xor_sync(0xFFFFFFFFu, c1, 4);
                float oc2 = __shfl_xor_sync(0xFFFFFFFFu, c2, 4);
                float oc3 = __shfl_xor_sync(0xFFFFFFFFu, c3, 4);
                if (!(g & 1)) {
                    int m = m0 + wm + mt * 16 + g;   // even key
                    int n = n0 + wn + nt * 8 + 2 * tk;
                    int b = m >> 11, key = m & 2047;
                    int hh = n >> 6, dl = n & 63;
                    uint32_t* base =
                        g_Vb + ((size_t)((b * NHEAD + hh) * HDIM + dl)) * KLEN;
                    uint2 o;
                    packsplit(c0, oc0, o.x, o.y);
                    *(uint2*)(base + key) = o;
                    packsplit(c2, oc2, o.x, o.y);
                    *(uint2*)(base + key + 8) = o;
                    packsplit(c1, oc1, o.x, o.y);
                    *(uint2*)(base + KLEN + key) = o;
                    packsplit(c3, oc3, o.x, o.y);
                    *(uint2*)(base + KLEN + key + 8) = o;
                }
            }
        }
    }
}

// Output projection: ctx2 @ Wo2^T -> plain fp32 out.
__global__ __launch_bounds__(256, 1) void gemm_out(float* __restrict__ out)
{
    extern __shared__ uint32_t smu[];
    const uint32_t* W2 = g_W2 + (size_t)3 * EMBED * RU;
    const int m0 = blockIdx.y * 256;
    const int n0 = blockIdx.x * 128;

    float acc[4][8][4];
    gemm_core(g_Cb, W2, smu, acc, m0, n0);

    const int lane = threadIdx.x & 31;
    const int w    = threadIdx.x >> 5;
    const int g    = lane >> 2;
    const int tk   = lane & 3;
    const int wm   = (w & 3) * 64;
    const int wn   = (w >> 2) * 64;
#pragma unroll
    for (int mt = 0; mt < 4; mt++) {
#pragma unroll
        for (int nt = 0; nt < 8; nt++) {
            int m = m0 + wm + mt * 16 + g;
            int n = n0 + wn + nt * 8 + 2 * tk;
            *(float2*)(out + (size_t)m * EMBED + n) =
                make_float2(acc[mt][nt][0], acc[mt][nt][1]);
            *(float2*)(out + (size_t)(m + 8) * EMBED + n) =
                make_float2(acc[mt][nt][2], acc[mt][nt][3]);
        }
    }
}

// ---------------------------------------------------------------------------
// Flash attention (unchanged from R9). Grid (QLEN/128, NHEAD, BATCH), 128 thr.
// ---------------------------------------------------------------------------
#define RA 72
#define ABUFU (64 * RA)                        // 4608 u32
#define ATT_SMEM (4 * ABUFU * 4)               // 73728 B

__device__ __forceinline__ void attn_load_tile(uint32_t sbase, int buf,
                                               int b, int h, int kt)
{
    const int tid = threadIdx.x;
    const uint32_t* Kg = g_Kb + (size_t)(b * KLEN + kt * 64) * RU + h * HDIM;
    const uint32_t* Vg = g_Vb + ((size_t)(b * NHEAD + h) * HDIM) * KLEN + kt * 64;
#pragma unroll
    for (int it = 0; it < 8; it++) {
        int l = tid + it * 128;
        int row = l >> 4, c = l & 15;
        cpa16(sbase + (uint32_t)((buf * ABUFU + row * RA + c * 4) * 4),
              Kg + (size_t)row * RU + c * 4);
        cpa16(sbase + (uint32_t)((2 * ABUFU + buf * ABUFU + row * RA + c * 4) * 4),
              Vg + (size_t)row * KLEN + c * 4);
    }
}

__global__ __launch_bounds__(128, 2) void attn_tc()
{
    extern __shared__ uint32_t smu[];
    uint32_t sbase = (uint32_t)__cvta_generic_to_shared(smu);

    const int tid  = threadIdx.x;
    const int lane = tid & 31;
    const int w    = tid >> 5;
    const int g    = lane >> 2;
    const int tk   = lane & 3;
    const int qt = blockIdx.x, h = blockIdx.y, b = blockIdx.z;
    const int q0 = qt * 128;
    const int wrow = w * 32;

    uint32_t qh[2][4][4], ql[2][4][4];
#pragma unroll
    for (int mt = 0; mt < 2; mt++) {
        const uint32_t* Qg =
            g_Qb + (size_t)(b * QLEN + q0 + wrow + mt * 16) * RU + h * HDIM;
#pragma unroll
        for (int kk = 0; kk < 4; kk++) {
            int cb = kk * 16 + 2 * tk;
            uint2 v;
            v = *(const uint2*)(Qg + (size_t)g * RU + cb);
            qh[mt][kk][0] = v.x; ql[mt][kk][0] = v.y;
            v = *(const uint2*)(Qg + (size_t)(g + 8) * RU + cb);
            qh[mt][kk][1] = v.x; ql[mt][kk][1] = v.y;
            v = *(const uint2*)(Qg + (size_t)g * RU + cb + 8);
            qh[mt][kk][2] = v.x; ql[mt][kk][2] = v.y;
            v = *(const uint2*)(Qg + (size_t)(g + 8) * RU + cb + 8);
            qh[mt][kk][3] = v.x; ql[mt][kk][3] = v.y;
        }
    }

    float oacc[2][8][4];
#pragma unroll
    for (int mt = 0; mt < 2; mt++)
#pragma unroll
        for (int nt = 0; nt < 8; nt++)
#pragma unroll
            for (int r = 0; r < 4; r++) oacc[mt][nt][r] = 0.f;
    float mrow[4] = {-INFINITY, -INFINITY, -INFINITY, -INFINITY};
    float lrow[4] = {0.f, 0.f, 0.f, 0.f};

    const float* penb = g_pen + (size_t)b * KLEN;
    const int T = KLEN / 64;
    attn_load_tile(sbase, 0, b, h, 0);
    cpa_commit();

    for (int kt = 0; kt < T; kt++) {
        if (kt + 1 < T) {
            attn_load_tile(sbase, (kt + 1) & 1, b, h, kt + 1);
            cpa_commit();
            cpa_wait<1>();
        } else {
            cpa_wait<0>();
        }
        __syncthreads();

        const uint32_t* Ks = smu + (kt & 1) * ABUFU;
        const uint32_t* Vs = smu + 2 * ABUFU + (kt & 1) * ABUFU;

        float sacc[2][8][4];
#pragma unroll
        for (int mt = 0; mt < 2; mt++)
#pragma unroll
            for (int nt = 0; nt < 8; nt++)
#pragma unroll
                for (int r = 0; r < 4; r++) sacc[mt][nt][r] = 0.f;

#pragma unroll
        for (int kk = 0; kk < 4; kk++) {
            const int cb = kk * 16 + 2 * tk;
#pragma unroll
            for (int nh = 0; nh < 2; nh++) {
                uint32_t bh[4][2], bl[4][2];
#pragma unroll
                for (int j = 0; j < 4; j++) {
                    int nr = ((nh * 4 + j) * 8 + g) * RA + cb;
                    uint2 b0 = *(const uint2*)&Ks[nr];
                    uint2 b1 = *(const uint2*)&Ks[nr + 8];
                    bh[j][0] = b0.x; bl[j][0] = b0.y;
                    bh[j][1] = b1.x; bl[j][1] = b1.y;
                }
#pragma unroll
                for (int j = 0; j < 4; j++)
#pragma unroll
                    for (int mt = 0; mt < 2; mt++)
                        mma16(sacc[mt][nh * 4 + j], qh[mt][kk], bh[j]);
#pragma unroll
                for (int j = 0; j < 4; j++)
#pragma unroll
                    for (int mt = 0; mt < 2; mt++)
                        mma16(sacc[mt][nh * 4 + j], ql[mt][kk], bh[j]);
#pragma unroll
                for (int j = 0; j < 4; j++)
#pragma unroll
                    for (int mt = 0; mt < 2; mt++)
                        mma16(sacc[mt][nh * 4 + j], qh[mt][kk], bl[j]);
            }
        }

        float2 p2[8];
#pragma unroll
        for (int nt = 0; nt < 8; nt++)
            p2[nt] = __ldg((const float2*)(penb + kt * 64 + nt * 8 + 2 * tk));

#pragma unroll
        for (int mt = 0; mt < 2; mt++) {
            float mx0 = -INFINITY, mx1 = -INFINITY;
#pragma unroll
            for (int nt = 0; nt < 8; nt++) {
                sacc[mt][nt][0] -= p2[nt].x; sacc[mt][nt][1] -= p2[nt].y;
                sacc[mt][nt][2] -= p2[nt].x; sacc[mt][nt][3] -= p2[nt].y;
                mx0 = fmaxf(mx0, fmaxf(sacc[mt][nt][0], sacc[mt][nt][1]));
                mx1 = fmaxf(mx1, fmaxf(sacc[mt][nt][2], sacc[mt][nt][3]));
            }
            mx0 = fmaxf(mx0, __shfl_xor_sync(0xFFFFFFFFu, mx0, 1));
            mx0 = fmaxf(mx0, __shfl_xor_sync(0xFFFFFFFFu, mx0, 2));
            mx1 = fmaxf(mx1, __shfl_xor_sync(0xFFFFFFFFu, mx1, 1));
            mx1 = fmaxf(mx1, __shfl_xor_sync(0xFFFFFFFFu, mx1, 2));

            const float mn0 = fmaxf(mrow[2 * mt], mx0);
            const float mn1 = fmaxf(mrow[2 * mt + 1], mx1);
            const float a0 = __expf(mrow[2 * mt] - mn0);
            const float a1 = __expf(mrow[2 * mt + 1] - mn1);
            float ls0 = 0.f, ls1 = 0.f;
#pragma unroll
            for (int nt = 0; nt < 8; nt++) {
                sacc[mt][nt][0] = __expf(sacc[mt][nt][0] - mn0);
                sacc[mt][nt][1] = __expf(sacc[mt][nt][1] - mn0);
                sacc[mt][nt][2] = __expf(sacc[mt][nt][2] - mn1);
                sacc[mt][nt][3] = __expf(sacc[mt][nt][3] - mn1);
                ls0 += sacc[mt][nt][0] + sacc[mt][nt][1];
                ls1 += sacc[mt][nt][2] + sacc[mt][nt][3];
            }
            ls0 += __shfl_xor_sync(0xFFFFFFFFu, ls0, 1);
            ls0 += __shfl_xor_sync(0xFFFFFFFFu, ls0, 2);
            ls1 += __shfl_xor_sync(0xFFFFFFFFu, ls1, 1);
            ls1 += __shfl_xor_sync(0xFFFFFFFFu, ls1, 2);
            lrow[2 * mt]     = lrow[2 * mt] * a0 + ls0;
            lrow[2 * mt + 1] = lrow[2 * mt + 1] * a1 + ls1;
            mrow[2 * mt] = mn0; mrow[2 * mt + 1] = mn1;
#pragma unroll
            for (int nt = 0; nt < 8; nt++) {
                oacc[mt][nt][0] *= a0; oacc[mt][nt][1] *= a0;
                oacc[mt][nt][2] *= a1; oacc[mt][nt][3] *= a1;
            }
        }

#pragma unroll
        for (int kk = 0; kk < 4; kk++) {
            uint32_t ph[2][4], pl[2][4];
#pragma unroll
            for (int mt = 0; mt < 2; mt++) {
                packsplit(sacc[mt][2 * kk][0],     sacc[mt][2 * kk][1],
                          ph[mt][0], pl[mt][0]);
                packsplit(sacc[mt][2 * kk][2],     sacc[mt][2 * kk][3],
                          ph[mt][1], pl[mt][1]);
                packsplit(sacc[mt][2 * kk + 1][0], sacc[mt][2 * kk + 1][1],
                          ph[mt][2], pl[mt][2]);
                packsplit(sacc[mt][2 * kk + 1][2], sacc[mt][2 * kk + 1][3],
                          ph[mt][3], pl[mt][3]);
            }
            const int cb = kk * 16 + 2 * tk;
#pragma unroll
            for (int nh = 0; nh < 2; nh++) {
                uint32_t vh[4][2], vl[4][2];
#pragma unroll
                for (int j = 0; j < 4; j++) {
                    int nr = ((nh * 4 + j) * 8 + g) * RA + cb;
                    uint2 v0 = *(const uint2*)&Vs[nr];
                    uint2 v1 = *(const uint2*)&Vs[nr + 8];
                    vh[j][0] = v0.x; vl[j][0] = v0.y;
                    vh[j][1] = v1.x; vl[j][1] = v1.y;
                }
#pragma unroll
                for (int j = 0; j < 4; j++)
#pragma unroll
                    for (int mt = 0; mt < 2; mt++)
                        mma16(oacc[mt][nh * 4 + j], ph[mt], vh[j]);
#pragma unroll
                for (int j = 0; j < 4; j++)
#pragma unroll
                    for (int mt = 0; mt < 2; mt++)
                        mma16(oacc[mt][nh * 4 + j], pl[mt], vh[j]);
#pragma unroll
                for (int j = 0; j < 4; j++)
#pragma unroll
                    for (int mt = 0; mt < 2; mt++)
                        mma16(oacc[mt][nh * 4 + j], ph[mt], vl[j]);
            }
        }
        __syncthreads();
    }

    // ---- epilogue: split-packed ctx for the output GEMM
#pragma unroll
    for (int mt = 0; mt < 2; mt++) {
        const float inv0 = 1.0f / lrow[2 * mt];
        const float inv1 = 1.0f / lrow[2 * mt + 1];
        uint32_t* c0p = g_Cb +
            (size_t)(b * QLEN + q0 + wrow + mt * 16 + g) * RU + h * HDIM;
        uint32_t* c1p = g_Cb +
            (size_t)(b * QLEN + q0 + wrow + mt * 16 + g + 8) * RU + h * HDIM;
#pragma unroll
        for (int nt = 0; nt < 8; nt++) {
            int d = nt * 8 + 2 * tk;
            uint2 o;
            packsplit(oacc[mt][nt][0] * inv0, oacc[mt][nt][1] * inv0, o.x, o.y);
            *(uint2*)(c0p + d) = o;
            packsplit(oacc[mt][nt][2] * inv1, oacc[mt][nt][3] * inv1, o.x, o.y);
            *(uint2*)(c1p + d) = o;
        }
    }
}

// ---------------------------------------------------------------------------
extern "C" void kernel_launch(void* const* d_in, const int* in_sizes, int n_in,
                              void* d_out, int out_size)
{
    (void)in_sizes; (void)n_in; (void)out_size;
    const float* query = (const float*)d_in[0];
    const float* key   = (const float*)d_in[1];
    const float* val   = (const float*)d_in[2];
    const int*   mask  = (const int*)  d_in[3];
    const float* Wq    = (const float*)d_in[4];
    const float* Wk    = (const float*)d_in[5];
    const float* Wv    = (const float*)d_in[6];
    const float* Wo    = (const float*)d_in[7];
    float* out = (float*)d_out;

    static int attrs_set = 0;
    if (!attrs_set) {
        cudaFuncSetAttribute(gemm_qkv,
                             cudaFuncAttributeMaxDynamicSharedMemorySize, GEMM_SMEM);
        cudaFuncSetAttribute(gemm_out,
                             cudaFuncAttributeMaxDynamicSharedMemorySize, GEMM_SMEM);
        cudaFuncSetAttribute(attn_tc,
                             cudaFuncAttributeMaxDynamicSharedMemorySize, ATT_SMEM);
        attrs_set = 1;
    }

    prep_split<<<2048, 256>>>(query, key, val, Wq, Wk, Wv, Wo, mask);

    dim3 gQKV(EMBED / 128, MROWS / 256, 3);     // (8, 16, 3)
    gemm_qkv<<<gQKV, 256, GEMM_SMEM>>>();

    dim3 gAttn(QLEN / 128, NHEAD, BATCH);       // (16, 16, 2)
    attn_tc<<<gAttn, 128, ATT_SMEM>>>();

    dim3 gOut(EMBED / 128, MROWS / 256);        // (8, 16)
    gemm_out<<<gOut, 256, GEMM_SMEM>>>(out);
}

// round 11
// speedup vs baseline: 1.5529x; 1.5529x over previous
#include <cuda_runtime.h>
#include <math.h>
#include <stdint.h>

#define EMBED 1024
#define NHEAD 16
#define HDIM  64
#define BATCH 2
#define QLEN  2048
#define KLEN  2048
#define MROWS (BATCH*QLEN)   // 4096
#define RU    1024           // u32 per 2-term packed row (1 u32 per element)
#define RK    512            // u32 per single-fp16 row of 1024 elems

// ---------------------------------------------------------------------------
// A-side format (2-term fp16 split): pair p -> u32[2p]=f16x2(hi x0,hi x1),
// u32[2p+1]=f16x2(lo x0,lo x1). B-side: single fp16, u32[e]=f16x2(x2e,x2e+1).
// ---------------------------------------------------------------------------
__device__ uint32_t g_in2[(size_t)3 * MROWS * RU];           // q,k,v inputs (2-term)
__device__ uint32_t g_Wh [(size_t)4 * EMBED * RK];           // weights (single)
__device__ uint32_t g_Qb [(size_t)MROWS * RU];               // Q (2-term, along d)
__device__ uint32_t g_Kb [(size_t)MROWS * RK];               // K (single, along d)
__device__ uint32_t g_Vb [(size_t)BATCH * NHEAD * HDIM * (KLEN/2)]; // V single [b][h][d][keypair]
__device__ uint32_t g_Cb [(size_t)MROWS * RU];               // ctx (2-term)
__device__ float    g_pen[(size_t)BATCH * KLEN];

// ---------------------------------------------------------------------------
// helpers
// ---------------------------------------------------------------------------
__device__ __forceinline__ uint32_t pack16(float x0, float x1) {
    uint32_t r;
    asm("cvt.rn.f16x2.f32 %0, %1, %2;" : "=r"(r) : "f"(x1), "f"(x0));
    return r;
}
__device__ __forceinline__ void packsplit16(float x0, float x1,
                                            uint32_t& hi, uint32_t& lo) {
    uint32_t h = pack16(x0, x1);
    float h0, h1;
    asm("{\n\t.reg .f16 a, b;\n\tmov.b32 {a, b}, %2;\n\t"
        "cvt.f32.f16 %0, a;\n\tcvt.f32.f16 %1, b;\n\t}"
        : "=f"(h0), "=f"(h1) : "r"(h));
    hi = h;
    lo = pack16(x0 - h0, x1 - h1);
}

__device__ __forceinline__ void mma16(float* c, const uint32_t* a, const uint32_t* b) {
    asm volatile(
        "mma.sync.aligned.m16n8k16.row.col.f32.f16.f16.f32 "
        "{%0,%1,%2,%3}, {%4,%5,%6,%7}, {%8,%9}, {%0,%1,%2,%3};\n"
        : "+f"(c[0]), "+f"(c[1]), "+f"(c[2]), "+f"(c[3])
        : "r"(a[0]), "r"(a[1]), "r"(a[2]), "r"(a[3]), "r"(b[0]), "r"(b[1]));
}

__device__ __forceinline__ void cpa16(uint32_t dst, const void* src) {
    asm volatile("cp.async.cg.shared.global [%0], [%1], 16;\n" :: "r"(dst), "l"(src));
}
__device__ __forceinline__ void cpa_commit() {
    asm volatile("cp.async.commit_group;\n");
}
template <int N>
__device__ __forceinline__ void cpa_wait() {
    asm volatile("cp.async.wait_group %0;\n" :: "n"(N));
}

// ---------------------------------------------------------------------------
// prep: inputs -> 2-term fp16 pairs; weights -> single fp16; mask -> penalty.
// ---------------------------------------------------------------------------
#define SEG_IN  ((size_t)MROWS * EMBED / 4)
#define SEG_W   ((size_t)EMBED * EMBED / 4)
#define N_IN    (3 * SEG_IN)
#define N_W     (4 * SEG_W)
#define N_MASK  ((size_t)BATCH * KLEN / 4)

__global__ __launch_bounds__(256) void prep_split(
    const float* __restrict__ q,  const float* __restrict__ k,
    const float* __restrict__ v,
    const float* __restrict__ wq, const float* __restrict__ wk,
    const float* __restrict__ wv, const float* __restrict__ wo,
    const int* __restrict__ mask)
{
    const size_t total = N_IN + N_W + N_MASK;
    for (size_t u = (size_t)blockIdx.x * blockDim.x + threadIdx.x; u < total;
         u += (size_t)gridDim.x * blockDim.x) {
        if (u < N_IN) {
            int which = (int)(u / SEG_IN);
            size_t off = u - (size_t)which * SEG_IN;
            const float* src = which == 0 ? q : which == 1 ? k : v;
            float sc = which == 0 ? (1.0f / 32.0f) : 1.0f;
            float4 x = ((const float4*)src)[off];
            uint4 o;
            packsplit16(x.x * sc, x.y * sc, o.x, o.y);
            packsplit16(x.z * sc, x.w * sc, o.z, o.w);
            ((uint4*)(g_in2 + (size_t)which * MROWS * RU))[off] = o;
        } else if (u < N_IN + N_W) {
            size_t uu = u - N_IN;
            int which = (int)(uu / SEG_W);
            size_t off = uu - (size_t)which * SEG_W;
            const float* src = which == 0 ? wq : which == 1 ? wk
                              : which == 2 ? wv : wo;
            float4 x = ((const float4*)src)[off];
            uint2 o;
            o.x = pack16(x.x, x.y);
            o.y = pack16(x.z, x.w);
            ((uint2*)(g_Wh + (size_t)which * EMBED * RK))[off] = o;
        } else {
            size_t off = u - N_IN - N_W;
            int4 m = ((const int4*)mask)[off];
            float4 p;
            p.x = m.x ? 10000.0f : 0.0f;
            p.y = m.y ? 10000.0f : 0.0f;
            p.z = m.z ? 10000.0f : 0.0f;
            p.w = m.w ? 10000.0f : 0.0f;
            ((float4*)g_pen)[off] = p;
        }
    }
}

// ---------------------------------------------------------------------------
// GEMM core: 128x128 tile, 128 thr = 4 warps (2m x 2n), warp 64x64, BK=32.
// A 2-term (stride 40 u32), B single fp16 (stride 20 u32), double buffered.
// 2 MMAs per k-step: Ah*B + Al*B.
// ---------------------------------------------------------------------------
#define RG 40
#define RB 20
#define GBUFA (128 * RG)                       // 5120 u32
#define GBUFB (128 * RB)                       // 2560 u32
#define GEMM_SMEM ((2 * GBUFA + 2 * GBUFB) * 4)   // 61440 B

__device__ __forceinline__ void gemm_load_tile(
    uint32_t sbase, int buf, const uint32_t* __restrict__ A2,
    const uint32_t* __restrict__ Wh, int m0, int n0, int t)
{
    const int tid = threadIdx.x;
    const int kofA = t * 32;
    const int kofB = t * 16;
#pragma unroll
    for (int it = 0; it < 8; it++) {
        int l = tid + it * 128;
        int row = l >> 3, c = l & 7;
        cpa16(sbase + (uint32_t)((buf * GBUFA + row * RG + c * 4) * 4),
              A2 + (size_t)(m0 + row) * RU + kofA + c * 4);
    }
#pragma unroll
    for (int it = 0; it < 4; it++) {
        int l = tid + it * 128;
        int row = l >> 2, c = l & 3;
        cpa16(sbase + (uint32_t)((2 * GBUFA + buf * GBUFB + row * RB + c * 4) * 4),
              Wh + (size_t)(n0 + row) * RK + kofB + c * 4);
    }
}

__device__ __forceinline__ void gemm_core(
    const uint32_t* __restrict__ A2, const uint32_t* __restrict__ Wh,
    uint32_t* smu, float acc[4][8][4], int m0, int n0)
{
    const int tid  = threadIdx.x;
    const int lane = tid & 31;
    const int w    = tid >> 5;
    const int g    = lane >> 2;
    const int tk   = lane & 3;
    const int wm   = (w & 1) * 64;
    const int wn   = (w >> 1) * 64;
    uint32_t sbase = (uint32_t)__cvta_generic_to_shared(smu);

#pragma unroll
    for (int mt = 0; mt < 4; mt++)
#pragma unroll
        for (int nt = 0; nt < 8; nt++)
#pragma unroll
            for (int r = 0; r < 4; r++) acc[mt][nt][r] = 0.f;

    const int T = EMBED / 32;   // 32 k-tiles
    gemm_load_tile(sbase, 0, A2, Wh, m0, n0, 0);
    cpa_commit();

    for (int t = 0; t < T; t++) {
        if (t + 1 < T) {
            gemm_load_tile(sbase, (t + 1) & 1, A2, Wh, m0, n0, t + 1);
            cpa_commit();
            cpa_wait<1>();
        } else {
            cpa_wait<0>();
        }
        __syncthreads();

        const uint32_t* As = smu + (t & 1) * GBUFA;
        const uint32_t* Bs = smu + 2 * GBUFA + (t & 1) * GBUFB;
#pragma unroll
        for (int kk = 0; kk < 2; kk++) {
            uint32_t ah[4][4], al[4][4];
            const int cb  = kk * 16 + 2 * tk;     // A pair index
            const int cb2 = kk * 8 + tk;          // B u32 index
#pragma unroll
            for (int mt = 0; mt < 4; mt++) {
                int rb = wm + mt * 16;
                uint2 v;
                v = *(const uint2*)&As[(rb + g) * RG + cb];
                ah[mt][0] = v.x; al[mt][0] = v.y;
                v = *(const uint2*)&As[(rb + g + 8) * RG + cb];
                ah[mt][1] = v.x; al[mt][1] = v.y;
                v = *(const uint2*)&As[(rb + g) * RG + cb + 8];
                ah[mt][2] = v.x; al[mt][2] = v.y;
                v = *(const uint2*)&As[(rb + g + 8) * RG + cb + 8];
                ah[mt][3] = v.x; al[mt][3] = v.y;
            }
#pragma unroll
            for (int nh = 0; nh < 2; nh++) {
                uint32_t bh[4][2];
#pragma unroll
                for (int j = 0; j < 4; j++) {
                    int nr = (wn + (nh * 4 + j) * 8 + g) * RB + cb2;
                    bh[j][0] = Bs[nr];
                    bh[j][1] = Bs[nr + 4];
                }
#pragma unroll
                for (int j = 0; j < 4; j++)
#pragma unroll
                    for (int mt = 0; mt < 4; mt++)
                        mma16(acc[mt][nh * 4 + j], ah[mt], bh[j]);
#pragma unroll
                for (int j = 0; j < 4; j++)
#pragma unroll
                    for (int mt = 0; mt < 4; mt++)
                        mma16(acc[mt][nh * 4 + j], al[mt], bh[j]);
            }
        }
        __syncthreads();
    }
}

// QKV projections: z = 0 (Q 2-term), 1 (K single), 2 (V transposed single).
__global__ __launch_bounds__(128, 2) void gemm_qkv()
{
    extern __shared__ uint32_t smu[];
    const int z = blockIdx.z;
    const uint32_t* A2 = g_in2 + (size_t)z * MROWS * RU;
    const uint32_t* Wh = g_Wh + (size_t)z * EMBED * RK;
    const int m0 = blockIdx.y * 128;
    const int n0 = blockIdx.x * 128;

    float acc[4][8][4];
    gemm_core(A2, Wh, smu, acc, m0, n0);

    const int lane = threadIdx.x & 31;
    const int w    = threadIdx.x >> 5;
    const int g    = lane >> 2;
    const int tk   = lane & 3;
    const int wm   = (w & 1) * 64;
    const int wn   = (w >> 1) * 64;

    if (z == 0) {
#pragma unroll
        for (int mt = 0; mt < 4; mt++) {
#pragma unroll
            for (int nt = 0; nt < 8; nt++) {
                int m = m0 + wm + mt * 16 + g;
                int n = n0 + wn + nt * 8 + 2 * tk;
                uint2 o;
                packsplit16(acc[mt][nt][0], acc[mt][nt][1], o.x, o.y);
                *(uint2*)(g_Qb + (size_t)m * RU + n) = o;
                packsplit16(acc[mt][nt][2], acc[mt][nt][3], o.x, o.y);
                *(uint2*)(g_Qb + (size_t)(m + 8) * RU + n) = o;
            }
        }
    } else if (z == 1) {
#pragma unroll
        for (int mt = 0; mt < 4; mt++) {
#pragma unroll
            for (int nt = 0; nt < 8; nt++) {
                int m = m0 + wm + mt * 16 + g;
                int n = n0 + wn + nt * 8 + 2 * tk;
                g_Kb[(size_t)m * RK + (n >> 1)] =
                    pack16(acc[mt][nt][0], acc[mt][nt][1]);
                g_Kb[(size_t)(m + 8) * RK + (n >> 1)] =
                    pack16(acc[mt][nt][2], acc[mt][nt][3]);
            }
        }
    } else {
        // V: [b][h][d][key-pair] single fp16; pair keys (g even/odd) via shfl.
#pragma unroll
        for (int mt = 0; mt < 4; mt++) {
#pragma unroll
            for (int nt = 0; nt < 8; nt++) {
                float c0 = acc[mt][nt][0], c1 = acc[mt][nt][1];
                float c2 = acc[mt][nt][2], c3 = acc[mt][nt][3];
                float oc0 = __shfl_xor_sync(0xFFFFFFFFu, c0, 4);
                float oc1 = __shfl_xor_sync(0xFFFFFFFFu, c1, 4);
                float oc2 = __shfl_xor_sync(0xFFFFFFFFu, c2, 4);
                float oc3 = __shfl_xor_sync(0xFFFFFFFFu, c3, 4);
                if (!(g & 1)) {
                    int m = m0 + wm + mt * 16 + g;   // even key
                    int n = n0 + wn + nt * 8 + 2 * tk;
                    int b = m >> 11, key = m & 2047;
                    int hh = n >> 6, dl = n & 63;
                    uint32_t* base = g_Vb +
                        ((size_t)((b * NHEAD + hh) * HDIM + dl)) * (KLEN / 2);
                    base[(key >> 1)]     = pack16(c0, oc0);
                    base[(key >> 1) + 4] = pack16(c2, oc2);
                    base[KLEN / 2 + (key >> 1)]     = pack16(c1, oc1);
                    base[KLEN / 2 + (key >> 1) + 4] = pack16(c3, oc3);
                }
            }
        }
    }
}

// Output projection: ctx (2-term) @ Wo (single) -> fp32 out.
__global__ __launch_bounds__(128, 2) void gemm_out(float* __restrict__ out)
{
    extern __shared__ uint32_t smu[];
    const uint32_t* Wh = g_Wh + (size_t)3 * EMBED * RK;
    const int m0 = blockIdx.y * 128;
    const int n0 = blockIdx.x * 128;

    float acc[4][8][4];
    gemm_core(g_Cb, Wh, smu, acc, m0, n0);

    const int lane = threadIdx.x & 31;
    const int w    = threadIdx.x >> 5;
    const int g    = lane >> 2;
    const int tk   = lane & 3;
    const int wm   = (w & 1) * 64;
    const int wn   = (w >> 1) * 64;
#pragma unroll
    for (int mt = 0; mt < 4; mt++) {
#pragma unroll
        for (int nt = 0; nt < 8; nt++) {
            int m = m0 + wm + mt * 16 + g;
            int n = n0 + wn + nt * 8 + 2 * tk;
            *(float2*)(out + (size_t)m * EMBED + n) =
                make_float2(acc[mt][nt][0], acc[mt][nt][1]);
            *(float2*)(out + (size_t)(m + 8) * EMBED + n) =
                make_float2(acc[mt][nt][2], acc[mt][nt][3]);
        }
    }
}

// ---------------------------------------------------------------------------
// Flash attention. Grid (QLEN/128, NHEAD, BATCH), 128 thr = 4 warps x 32 rows.
// Q 2-term in regs; K/V single fp16 in smem (stride 36 u32), double buffered.
// S = Qh*K + Ql*K ; PV = Ph*V + Pl*V.
// ---------------------------------------------------------------------------
#define RA 36
#define ABUF (64 * RA)                         // 2304 u32
#define ATT_SMEM (4 * ABUF * 4)                // 36864 B

__device__ __forceinline__ void attn_load_tile(uint32_t sbase, int buf,
                                               int b, int h, int kt)
{
    const int tid = threadIdx.x;
    const uint32_t* Kg = g_Kb + (size_t)(b * KLEN + kt * 64) * RK + h * (HDIM / 2);
    const uint32_t* Vg = g_Vb + ((size_t)(b * NHEAD + h) * HDIM) * (KLEN / 2)
                              + kt * 32;
#pragma unroll
    for (int it = 0; it < 4; it++) {
        int l = tid + it * 128;
        int row = l >> 3, c = l & 7;
        cpa16(sbase + (uint32_t)((buf * ABUF + row * RA + c * 4) * 4),
              Kg + (size_t)row * RK + c * 4);
        cpa16(sbase + (uint32_t)((2 * ABUF + buf * ABUF + row * RA + c * 4) * 4),
              Vg + (size_t)row * (KLEN / 2) + c * 4);
    }
}

__global__ __launch_bounds__(128, 2) void attn_tc()
{
    extern __shared__ uint32_t smu[];
    uint32_t sbase = (uint32_t)__cvta_generic_to_shared(smu);

    const int tid  = threadIdx.x;
    const int lane = tid & 31;
    const int w    = tid >> 5;
    const int g    = lane >> 2;
    const int tk   = lane & 3;
    const int qt = blockIdx.x, h = blockIdx.y, b = blockIdx.z;
    const int q0 = qt * 128;
    const int wrow = w * 32;

    // Q fragments (2-term) from packed gmem: 2 m-tiles x 4 k-tiles
    uint32_t qh[2][4][4], ql[2][4][4];
#pragma unroll
    for (int mt = 0; mt < 2; mt++) {
        const uint32_t* Qg =
            g_Qb + (size_t)(b * QLEN + q0 + wrow + mt * 16) * RU + h * HDIM;
#pragma unroll
        for (int kk = 0; kk < 4; kk++) {
            int cb = kk * 16 + 2 * tk;
            uint2 v;
            v = *(const uint2*)(Qg + (size_t)g * RU + cb);
            qh[mt][kk][0] = v.x; ql[mt][kk][0] = v.y;
            v = *(const uint2*)(Qg + (size_t)(g + 8) * RU + cb);
            qh[mt][kk][1] = v.x; ql[mt][kk][1] = v.y;
            v = *(const uint2*)(Qg + (size_t)g * RU + cb + 8);
            qh[mt][kk][2] = v.x; ql[mt][kk][2] = v.y;
            v = *(const uint2*)(Qg + (size_t)(g + 8) * RU + cb + 8);
            qh[mt][kk][3] = v.x; ql[mt][kk][3] = v.y;
        }
    }

    float oacc[2][8][4];
#pragma unroll
    for (int mt = 0; mt < 2; mt++)
#pragma unroll
        for (int nt = 0; nt < 8; nt++)
#pragma unroll
            for (int r = 0; r < 4; r++) oacc[mt][nt][r] = 0.f;
    float mrow[4] = {-INFINITY, -INFINITY, -INFINITY, -INFINITY};
    float lrow[4] = {0.f, 0.f, 0.f, 0.f};

    const float* penb = g_pen + (size_t)b * KLEN;
    const int T = KLEN / 64;
    attn_load_tile(sbase, 0, b, h, 0);
    cpa_commit();

    for (int kt = 0; kt < T; kt++) {
        if (kt + 1 < T) {
            attn_load_tile(sbase, (kt + 1) & 1, b, h, kt + 1);
            cpa_commit();
            cpa_wait<1>();
        } else {
            cpa_wait<0>();
        }
        __syncthreads();

        const uint32_t* Ks = smu + (kt & 1) * ABUF;
        const uint32_t* Vs = smu + 2 * ABUF + (kt & 1) * ABUF;

        // ---- S = Q @ K^T (32 q-rows x 64 keys per warp)
        float sacc[2][8][4];
#pragma unroll
        for (int mt = 0; mt < 2; mt++)
#pragma unroll
            for (int nt = 0; nt < 8; nt++)
#pragma unroll
                for (int r = 0; r < 4; r++) sacc[mt][nt][r] = 0.f;

#pragma unroll
        for (int kk = 0; kk < 4; kk++) {
            const int cb2 = kk * 8 + tk;
#pragma unroll
            for (int nh = 0; nh < 2; nh++) {
                uint32_t bh[4][2];
#pragma unroll
                for (int j = 0; j < 4; j++) {
                    int nr = ((nh * 4 + j) * 8 + g) * RA + cb2;
                    bh[j][0] = Ks[nr];
                    bh[j][1] = Ks[nr + 4];
                }
#pragma unroll
                for (int j = 0; j < 4; j++)
#pragma unroll
                    for (int mt = 0; mt < 2; mt++)
                        mma16(sacc[mt][nh * 4 + j], qh[mt][kk], bh[j]);
#pragma unroll
                for (int j = 0; j < 4; j++)
#pragma unroll
                    for (int mt = 0; mt < 2; mt++)
                        mma16(sacc[mt][nh * 4 + j], ql[mt][kk], bh[j]);
            }
        }

        // ---- mask + online softmax
        float2 p2[8];
#pragma unroll
        for (int nt = 0; nt < 8; nt++)
            p2[nt] = __ldg((const float2*)(penb + kt * 64 + nt * 8 + 2 * tk));

#pragma unroll
        for (int mt = 0; mt < 2; mt++) {
            float mx0 = -INFINITY, mx1 = -INFINITY;
#pragma unroll
            for (int nt = 0; nt < 8; nt++) {
                sacc[mt][nt][0] -= p2[nt].x; sacc[mt][nt][1] -= p2[nt].y;
                sacc[mt][nt][2] -= p2[nt].x; sacc[mt][nt][3] -= p2[nt].y;
                mx0 = fmaxf(mx0, fmaxf(sacc[mt][nt][0], sacc[mt][nt][1]));
                mx1 = fmaxf(mx1, fmaxf(sacc[mt][nt][2], sacc[mt][nt][3]));
            }
            mx0 = fmaxf(mx0, __shfl_xor_sync(0xFFFFFFFFu, mx0, 1));
            mx0 = fmaxf(mx0, __shfl_xor_sync(0xFFFFFFFFu, mx0, 2));
            mx1 = fmaxf(mx1, __shfl_xor_sync(0xFFFFFFFFu, mx1, 1));
            mx1 = fmaxf(mx1, __shfl_xor_sync(0xFFFFFFFFu, mx1, 2));

            const float mn0 = fmaxf(mrow[2 * mt], mx0);
            const float mn1 = fmaxf(mrow[2 * mt + 1], mx1);
            const float a0 = __expf(mrow[2 * mt] - mn0);
            const float a1 = __expf(mrow[2 * mt + 1] - mn1);
            float ls0 = 0.f, ls1 = 0.f;
#pragma unroll
            for (int nt = 0; nt < 8; nt++) {
                sacc[mt][nt][0] = __expf(sacc[mt][nt][0] - mn0);
                sacc[mt][nt][1] = __expf(sacc[mt][nt][1] - mn0);
                sacc[mt][nt][2] = __expf(sacc[mt][nt][2] - mn1);
                sacc[mt][nt][3] = __expf(sacc[mt][nt][3] - mn1);
                ls0 += sacc[mt][nt][0] + sacc[mt][nt][1];
                ls1 += sacc[mt][nt][2] + sacc[mt][nt][3];
            }
            ls0 += __shfl_xor_sync(0xFFFFFFFFu, ls0, 1);
            ls0 += __shfl_xor_sync(0xFFFFFFFFu, ls0, 2);
            ls1 += __shfl_xor_sync(0xFFFFFFFFu, ls1, 1);
            ls1 += __shfl_xor_sync(0xFFFFFFFFu, ls1, 2);
            lrow[2 * mt]     = lrow[2 * mt] * a0 + ls0;
            lrow[2 * mt + 1] = lrow[2 * mt + 1] * a1 + ls1;
            mrow[2 * mt] = mn0; mrow[2 * mt + 1] = mn1;
#pragma unroll
            for (int nt = 0; nt < 8; nt++) {
                oacc[mt][nt][0] *= a0; oacc[mt][nt][1] *= a0;
                oacc[mt][nt][2] *= a1; oacc[mt][nt][3] *= a1;
            }
        }

        // ---- PV: P 2-term fragments from sacc (C layout == A layout)
#pragma unroll
        for (int kk = 0; kk < 4; kk++) {
            uint32_t ph[2][4], pl[2][4];
#pragma unroll
            for (int mt = 0; mt < 2; mt++) {
                packsplit16(sacc[mt][2 * kk][0],     sacc[mt][2 * kk][1],
                            ph[mt][0], pl[mt][0]);
                packsplit16(sacc[mt][2 * kk][2],     sacc[mt][2 * kk][3],
                            ph[mt][1], pl[mt][1]);
                packsplit16(sacc[mt][2 * kk + 1][0], sacc[mt][2 * kk + 1][1],
                            ph[mt][2], pl[mt][2]);
                packsplit16(sacc[mt][2 * kk + 1][2], sacc[mt][2 * kk + 1][3],
                            ph[mt][3], pl[mt][3]);
            }
            const int cb2 = kk * 8 + tk;
#pragma unroll
            for (int nh = 0; nh < 2; nh++) {
                uint32_t vh[4][2];
#pragma unroll
                for (int j = 0; j < 4; j++) {
                    int nr = ((nh * 4 + j) * 8 + g) * RA + cb2;
                    vh[j][0] = Vs[nr];
                    vh[j][1] = Vs[nr + 4];
                }
#pragma unroll
                for (int j = 0; j < 4; j++)
#pragma unroll
                    for (int mt = 0; mt < 2; mt++)
                        mma16(oacc[mt][nh * 4 + j], ph[mt], vh[j]);
#pragma unroll
                for (int j = 0; j < 4; j++)
#pragma unroll
                    for (int mt = 0; mt < 2; mt++)
                        mma16(oacc[mt][nh * 4 + j], pl[mt], vh[j]);
            }
        }
        __syncthreads();
    }

    // ---- epilogue: 2-term packed ctx for the output GEMM
#pragma unroll
    for (int mt = 0; mt < 2; mt++) {
        const float inv0 = 1.0f / lrow[2 * mt];
        const float inv1 = 1.0f / lrow[2 * mt + 1];
        uint32_t* c0p = g_Cb +
            (size_t)(b * QLEN + q0 + wrow + mt * 16 + g) * RU + h * HDIM;
        uint32_t* c1p = g_Cb +
            (size_t)(b * QLEN + q0 + wrow + mt * 16 + g + 8) * RU + h * HDIM;
#pragma unroll
        for (int nt = 0; nt < 8; nt++) {
            int d = nt * 8 + 2 * tk;
            uint2 o;
            packsplit16(oacc[mt][nt][0] * inv0, oacc[mt][nt][1] * inv0, o.x, o.y);
            *(uint2*)(c0p + d) = o;
            packsplit16(oacc[mt][nt][2] * inv1, oacc[mt][nt][3] * inv1, o.x, o.y);
            *(uint2*)(c1p + d) = o;
        }
    }
}

// ---------------------------------------------------------------------------
extern "C" void kernel_launch(void* const* d_in, const int* in_sizes, int n_in,
                              void* d_out, int out_size)
{
    (void)in_sizes; (void)n_in; (void)out_size;
    const float* query = (const float*)d_in[0];
    const float* key   = (const float*)d_in[1];
    const float* val   = (const float*)d_in[2];
    const int*   mask  = (const int*)  d_in[3];
    const float* Wq    = (const float*)d_in[4];
    const float* Wk    = (const float*)d_in[5];
    const float* Wv    = (const float*)d_in[6];
    const float* Wo    = (const float*)d_in[7];
    float* out = (float*)d_out;

    static int attrs_set = 0;
    if (!attrs_set) {
        cudaFuncSetAttribute(gemm_qkv,
                             cudaFuncAttributeMaxDynamicSharedMemorySize, GEMM_SMEM);
        cudaFuncSetAttribute(gemm_out,
                             cudaFuncAttributeMaxDynamicSharedMemorySize, GEMM_SMEM);
        cudaFuncSetAttribute(attn_tc,
                             cudaFuncAttributeMaxDynamicSharedMemorySize, ATT_SMEM);
        attrs_set = 1;
    }

    prep_split<<<2048, 256>>>(query, key, val, Wq, Wk, Wv, Wo, mask);

    dim3 gQKV(EMBED / 128, MROWS / 128, 3);     // (8, 32, 3)
    gemm_qkv<<<gQKV, 128, GEMM_SMEM>>>();

    dim3 gAttn(QLEN / 128, NHEAD, BATCH);       // (16, 16, 2)
    attn_tc<<<gAttn, 128, ATT_SMEM>>>();

    dim3 gOut(EMBED / 128, MROWS / 128);        // (8, 32)
    gemm_out<<<gOut, 128, GEMM_SMEM>>>(out);
}

// round 13
// speedup vs baseline: 2.3681x; 1.5250x over previous
#include <cuda_runtime.h>
#include <math.h>
#include <stdint.h>

#define EMBED 1024
#define NHEAD 16
#define HDIM  64
#define BATCH 2
#define QLEN  2048
#define KLEN  2048
#define MROWS (BATCH*QLEN)   // 4096
#define RK    512            // u32 per fp16 row of 1024 elems (f16x2 packed)

// ---------------------------------------------------------------------------
// All operands single fp16 (f16x2 packed along the k/pack axis), fp32 accum.
// ---------------------------------------------------------------------------
__device__ uint32_t g_inh[(size_t)3 * MROWS * RK];           // q,k,v inputs
__device__ uint32_t g_Wh [(size_t)4 * EMBED * RK];           // Wq,Wk,Wv,Wo
__device__ uint32_t g_Qh [(size_t)MROWS * RK];               // Q (packed along d)
__device__ uint32_t g_Kb [(size_t)MROWS * RK];               // K (packed along d)
__device__ uint32_t g_Vb [(size_t)BATCH * NHEAD * HDIM * (KLEN/2)]; // V [b][h][d][keypair]
__device__ uint32_t g_Ch [(size_t)MROWS * RK];               // ctx
__device__ float    g_pen[(size_t)BATCH * KLEN];

// ---------------------------------------------------------------------------
// helpers
// ---------------------------------------------------------------------------
__device__ __forceinline__ uint32_t pack16(float x0, float x1) {
    uint32_t r;
    asm("cvt.rn.f16x2.f32 %0, %1, %2;" : "=r"(r) : "f"(x1), "f"(x0));
    return r;
}

__device__ __forceinline__ void mma16(float* c, const uint32_t* a, const uint32_t* b) {
    asm volatile(
        "mma.sync.aligned.m16n8k16.row.col.f32.f16.f16.f32 "
        "{%0,%1,%2,%3}, {%4,%5,%6,%7}, {%8,%9}, {%0,%1,%2,%3};\n"
        : "+f"(c[0]), "+f"(c[1]), "+f"(c[2]), "+f"(c[3])
        : "r"(a[0]), "r"(a[1]), "r"(a[2]), "r"(a[3]), "r"(b[0]), "r"(b[1]));
}

__device__ __forceinline__ void cpa16(uint32_t dst, const void* src) {
    asm volatile("cp.async.cg.shared.global [%0], [%1], 16;\n" :: "r"(dst), "l"(src));
}
__device__ __forceinline__ void cpa_commit() {
    asm volatile("cp.async.commit_group;\n");
}
template <int N>
__device__ __forceinline__ void cpa_wait() {
    asm volatile("cp.async.wait_group %0;\n" :: "n"(N));
}

// ---------------------------------------------------------------------------
// prep: inputs/weights -> single fp16; mask -> penalty floats.
// ---------------------------------------------------------------------------
#define SEG_IN  ((size_t)MROWS * EMBED / 4)
#define SEG_W   ((size_t)EMBED * EMBED / 4)
#define N_IN    (3 * SEG_IN)
#define N_W     (4 * SEG_W)
#define N_MASK  ((size_t)BATCH * KLEN / 4)

__global__ __launch_bounds__(256) void prep_split(
    const float* __restrict__ q,  const float* __restrict__ k,
    const float* __restrict__ v,
    const float* __restrict__ wq, const float* __restrict__ wk,
    const float* __restrict__ wv, const float* __restrict__ wo,
    const int* __restrict__ mask)
{
    const size_t total = N_IN + N_W + N_MASK;
    for (size_t u = (size_t)blockIdx.x * blockDim.x + threadIdx.x; u < total;
         u += (size_t)gridDim.x * blockDim.x) {
        if (u < N_IN) {
            int which = (int)(u / SEG_IN);
            size_t off = u - (size_t)which * SEG_IN;
            const float* src = which == 0 ? q : which == 1 ? k : v;
            float sc = which == 0 ? (1.0f / 32.0f) : 1.0f;
            float4 x = ((const float4*)src)[off];
            uint2 o;
            o.x = pack16(x.x * sc, x.y * sc);
            o.y = pack16(x.z * sc, x.w * sc);
            ((uint2*)(g_inh + (size_t)which * MROWS * RK))[off] = o;
        } else if (u < N_IN + N_W) {
            size_t uu = u - N_IN;
            int which = (int)(uu / SEG_W);
            size_t off = uu - (size_t)which * SEG_W;
            const float* src = which == 0 ? wq : which == 1 ? wk
                              : which == 2 ? wv : wo;
            float4 x = ((const float4*)src)[off];
            uint2 o;
            o.x = pack16(x.x, x.y);
            o.y = pack16(x.z, x.w);
            ((uint2*)(g_Wh + (size_t)which * EMBED * RK))[off] = o;
        } else {
            size_t off = u - N_IN - N_W;
            int4 m = ((const int4*)mask)[off];
            float4 p;
            p.x = m.x ? 10000.0f : 0.0f;
            p.y = m.y ? 10000.0f : 0.0f;
            p.z = m.z ? 10000.0f : 0.0f;
            p.w = m.w ? 10000.0f : 0.0f;
            ((float4*)g_pen)[off] = p;
        }
    }
}

// ---------------------------------------------------------------------------
// GEMM core: 128x128 tile, 128 thr = 4 warps (2m x 2n), warp 64x64, BK=32.
// Both operands single fp16, smem stride 20 u32 (16 data + 4 pad), dbl buf.
// ---------------------------------------------------------------------------
#define RG 20
#define GBUF (128 * RG)                        // 2560 u32
#define GEMM_SMEM (4 * GBUF * 4)               // 40960 B

__device__ __forceinline__ void gemm_load_tile(
    uint32_t sbase, int buf, const uint32_t* __restrict__ Ah,
    const uint32_t* __restrict__ Wh, int m0, int n0, int t)
{
    const int tid = threadIdx.x;
    const int kof = t * 16;                    // u32 per BK=32 elems
#pragma unroll
    for (int it = 0; it < 4; it++) {
        int l = tid + it * 128;
        int row = l >> 2, c = l & 3;
        cpa16(sbase + (uint32_t)((buf * GBUF + row * RG + c * 4) * 4),
              Ah + (size_t)(m0 + row) * RK + kof + c * 4);
    }
#pragma unroll
    for (int it = 0; it < 4; it++) {
        int l = tid + it * 128;
        int row = l >> 2, c = l & 3;
        cpa16(sbase + (uint32_t)((2 * GBUF + buf * GBUF + row * RG + c * 4) * 4),
              Wh + (size_t)(n0 + row) * RK + kof + c * 4);
    }
}

__device__ __forceinline__ void gemm_core(
    const uint32_t* __restrict__ Ah, const uint32_t* __restrict__ Wh,
    uint32_t* smu, float acc[4][8][4], int m0, int n0)
{
    const int tid  = threadIdx.x;
    const int lane = tid & 31;
    const int w    = tid >> 5;
    const int g    = lane >> 2;
    const int tk   = lane & 3;
    const int wm   = (w & 1) * 64;
    const int wn   = (w >> 1) * 64;
    uint32_t sbase = (uint32_t)__cvta_generic_to_shared(smu);

#pragma unroll
    for (int mt = 0; mt < 4; mt++)
#pragma unroll
        for (int nt = 0; nt < 8; nt++)
#pragma unroll
            for (int r = 0; r < 4; r++) acc[mt][nt][r] = 0.f;

    const int T = EMBED / 32;   // 32 k-tiles
    gemm_load_tile(sbase, 0, Ah, Wh, m0, n0, 0);
    cpa_commit();

    for (int t = 0; t < T; t++) {
        if (t + 1 < T) {
            gemm_load_tile(sbase, (t + 1) & 1, Ah, Wh, m0, n0, t + 1);
            cpa_commit();
            cpa_wait<1>();
        } else {
            cpa_wait<0>();
        }
        __syncthreads();

        const uint32_t* As = smu + (t & 1) * GBUF;
        const uint32_t* Bs = smu + 2 * GBUF + (t & 1) * GBUF;
#pragma unroll
        for (int kk = 0; kk < 2; kk++) {
            const int cb2 = kk * 8 + tk;
            uint32_t ah[4][4];
#pragma unroll
            for (int mt = 0; mt < 4; mt++) {
                int rb = wm + mt * 16;
                ah[mt][0] = As[(rb + g) * RG + cb2];
                ah[mt][1] = As[(rb + g + 8) * RG + cb2];
                ah[mt][2] = As[(rb + g) * RG + cb2 + 4];
                ah[mt][3] = As[(rb + g + 8) * RG + cb2 + 4];
            }
#pragma unroll
            for (int nh = 0; nh < 2; nh++) {
                uint32_t bh[4][2];
#pragma unroll
                for (int j = 0; j < 4; j++) {
                    int nr = (wn + (nh * 4 + j) * 8 + g) * RG + cb2;
                    bh[j][0] = Bs[nr];
                    bh[j][1] = Bs[nr + 4];
                }
#pragma unroll
                for (int j = 0; j < 4; j++)
#pragma unroll
                    for (int mt = 0; mt < 4; mt++)
                        mma16(acc[mt][nh * 4 + j], ah[mt], bh[j]);
            }
        }
        __syncthreads();
    }
}

// QKV projections: z = 0 (Q), 1 (K), 2 (V transposed). All fp16 outputs.
__global__ __launch_bounds__(128, 2) void gemm_qkv()
{
    extern __shared__ uint32_t smu[];
    const int z = blockIdx.z;
    const uint32_t* Ah = g_inh + (size_t)z * MROWS * RK;
    const uint32_t* Wh = g_Wh + (size_t)z * EMBED * RK;
    const int m0 = blockIdx.y * 128;
    const int n0 = blockIdx.x * 128;

    float acc[4][8][4];
    gemm_core(Ah, Wh, smu, acc, m0, n0);

    const int lane = threadIdx.x & 31;
    const int w    = threadIdx.x >> 5;
    const int g    = lane >> 2;
    const int tk   = lane & 3;
    const int wm   = (w & 1) * 64;
    const int wn   = (w >> 1) * 64;

    if (z < 2) {
        uint32_t* C2 = z == 0 ? g_Qh : g_Kb;
#pragma unroll
        for (int mt = 0; mt < 4; mt++) {
#pragma unroll
            for (int nt = 0; nt < 8; nt++) {
                int m = m0 + wm + mt * 16 + g;
                int n = n0 + wn + nt * 8 + 2 * tk;
                C2[(size_t)m * RK + (n >> 1)] =
                    pack16(acc[mt][nt][0], acc[mt][nt][1]);
                C2[(size_t)(m + 8) * RK + (n >> 1)] =
                    pack16(acc[mt][nt][2], acc[mt][nt][3]);
            }
        }
    } else {
        // V: [b][h][d][key-pair] fp16; pair keys (g even/odd) via shfl.
#pragma unroll
        for (int mt = 0; mt < 4; mt++) {
#pragma unroll
            for (int nt = 0; nt < 8; nt++) {
                float c0 = acc[mt][nt][0], c1 = acc[mt][nt][1];
                float c2 = acc[mt][nt][2], c3 = acc[mt][nt][3];
                float oc0 = __shfl_xor_sync(0xFFFFFFFFu, c0, 4);
                float oc1 = __shfl_xor_sync(0xFFFFFFFFu, c1, 4);
                float oc2 = __shfl_xor_sync(0xFFFFFFFFu, c2, 4);
                float oc3 = __shfl_xor_sync(0xFFFFFFFFu, c3, 4);
                if (!(g & 1)) {
                    int m = m0 + wm + mt * 16 + g;   // even key
                    int n = n0 + wn + nt * 8 + 2 * tk;
                    int b = m >> 11, key = m & 2047;
                    int hh = n >> 6, dl = n & 63;
                    uint32_t* base = g_Vb +
                        ((size_t)((b * NHEAD + hh) * HDIM + dl)) * (KLEN / 2);
                    base[(key >> 1)]     = pack16(c0, oc0);
                    base[(key >> 1) + 4] = pack16(c2, oc2);
                    base[KLEN / 2 + (key >> 1)]     = pack16(c1, oc1);
                    base[KLEN / 2 + (key >> 1) + 4] = pack16(c3, oc3);
                }
            }
        }
    }
}

// Output projection: ctx @ Wo^T -> fp32 out.
__global__ __launch_bounds__(128, 2) void gemm_out(float* __restrict__ out)
{
    extern __shared__ uint32_t smu[];
    const uint32_t* Wh = g_Wh + (size_t)3 * EMBED * RK;
    const int m0 = blockIdx.y * 128;
    const int n0 = blockIdx.x * 128;

    float acc[4][8][4];
    gemm_core(g_Ch, Wh, smu, acc, m0, n0);

    const int lane = threadIdx.x & 31;
    const int w    = threadIdx.x >> 5;
    const int g    = lane >> 2;
    const int tk   = lane & 3;
    const int wm   = (w & 1) * 64;
    const int wn   = (w >> 1) * 64;
#pragma unroll
    for (int mt = 0; mt < 4; mt++) {
#pragma unroll
        for (int nt = 0; nt < 8; nt++) {
            int m = m0 + wm + mt * 16 + g;
            int n = n0 + wn + nt * 8 + 2 * tk;
            *(float2*)(out + (size_t)m * EMBED + n) =
                make_float2(acc[mt][nt][0], acc[mt][nt][1]);
            *(float2*)(out + (size_t)(m + 8) * EMBED + n) =
                make_float2(acc[mt][nt][2], acc[mt][nt][3]);
        }
    }
}

// ---------------------------------------------------------------------------
// Flash attention. Grid (QLEN/128, NHEAD, BATCH), 128 thr = 4 warps x 32 rows.
// All operands single fp16; K/V smem rows of 32 data u32, stride RA=36.
// ---------------------------------------------------------------------------
#define RA 36
#define ABUF (64 * RA)                         // 2304 u32
#define ATT_SMEM (4 * ABUF * 4)                // 36864 B

__device__ __forceinline__ void attn_load_tile(uint32_t sbase, int buf,
                                               int b, int h, int kt)
{
    const int tid = threadIdx.x;
    const uint32_t* Kg = g_Kb + (size_t)(b * KLEN + kt * 64) * RK + h * (HDIM / 2);
    const uint32_t* Vg = g_Vb + ((size_t)(b * NHEAD + h) * HDIM) * (KLEN / 2)
                              + kt * 32;
#pragma unroll
    for (int it = 0; it < 4; it++) {
        int l = tid + it * 128;
        int row = l >> 3, c = l & 7;               // 64 rows x 32 u32
        cpa16(sbase + (uint32_t)((buf * ABUF + row * RA + c * 4) * 4),
              Kg + (size_t)row * RK + c * 4);
        cpa16(sbase + (uint32_t)((2 * ABUF + buf * ABUF + row * RA + c * 4) * 4),
              Vg + (size_t)row * (KLEN / 2) + c * 4);
    }
}

__global__ __launch_bounds__(128, 2) void attn_tc()
{
    extern __shared__ uint32_t smu[];
    uint32_t sbase = (uint32_t)__cvta_generic_to_shared(smu);

    const int tid  = threadIdx.x;
    const int lane = tid & 31;
    const int w    = tid >> 5;
    const int g    = lane >> 2;
    const int tk   = lane & 3;
    const int qt = blockIdx.x, h = blockIdx.y, b = blockIdx.z;
    const int q0 = qt * 128;
    const int wrow = w * 32;

    // Q fragments (single fp16): 2 m-tiles x 4 k-tiles
    uint32_t qh[2][4][4];
#pragma unroll
    for (int mt = 0; mt < 2; mt++) {
        const uint32_t* Qg =
            g_Qh + (size_t)(b * QLEN + q0 + wrow + mt * 16) * RK + h * (HDIM / 2);
#pragma unroll
        for (int kk = 0; kk < 4; kk++) {
            int cb2 = kk * 8 + tk;
            qh[mt][kk][0] = Qg[(size_t)g * RK + cb2];
            qh[mt][kk][1] = Qg[(size_t)(g + 8) * RK + cb2];
            qh[mt][kk][2] = Qg[(size_t)g * RK + cb2 + 4];
            qh[mt][kk][3] = Qg[(size_t)(g + 8) * RK + cb2 + 4];
        }
    }

    float oacc[2][8][4];
#pragma unroll
    for (int mt = 0; mt < 2; mt++)
#pragma unroll
        for (int nt = 0; nt < 8; nt++)
#pragma unroll
            for (int r = 0; r < 4; r++) oacc[mt][nt][r] = 0.f;
    float mrow[4] = {-INFINITY, -INFINITY, -INFINITY, -INFINITY};
    float lrow[4] = {0.f, 0.f, 0.f, 0.f};

    const float* penb = g_pen + (size_t)b * KLEN;
    const int T = KLEN / 64;
    attn_load_tile(sbase, 0, b, h, 0);
    cpa_commit();

    for (int kt = 0; kt < T; kt++) {
        if (kt + 1 < T) {
            attn_load_tile(sbase, (kt + 1) & 1, b, h, kt + 1);
            cpa_commit();
            cpa_wait<1>();
        } else {
            cpa_wait<0>();
        }
        __syncthreads();

        const uint32_t* Ks = smu + (kt & 1) * ABUF;
        const uint32_t* Vs = smu + 2 * ABUF + (kt & 1) * ABUF;

        // ---- S = Q @ K^T (32 q-rows x 64 keys per warp)
        float sacc[2][8][4];
#pragma unroll
        for (int mt = 0; mt < 2; mt++)
#pragma unroll
            for (int nt = 0; nt < 8; nt++)
#pragma unroll
                for (int r = 0; r < 4; r++) sacc[mt][nt][r] = 0.f;

#pragma unroll
        for (int kk = 0; kk < 4; kk++) {
            const int cb2 = kk * 8 + tk;
#pragma unroll
            for (int nh = 0; nh < 2; nh++) {
                uint32_t bh[4][2];
#pragma unroll
                for (int j = 0; j < 4; j++) {
                    int nr = ((nh * 4 + j) * 8 + g) * RA + cb2;
                    bh[j][0] = Ks[nr];
                    bh[j][1] = Ks[nr + 4];
                }
#pragma unroll
                for (int j = 0; j < 4; j++)
#pragma unroll
                    for (int mt = 0; mt < 2; mt++)
                        mma16(sacc[mt][nh * 4 + j], qh[mt][kk], bh[j]);
            }
        }

        // ---- mask + online softmax
        float2 p2[8];
#pragma unroll
        for (int nt = 0; nt < 8; nt++)
            p2[nt] = __ldg((const float2*)(penb + kt * 64 + nt * 8 + 2 * tk));

#pragma unroll
        for (int mt = 0; mt < 2; mt++) {
            float mx0 = -INFINITY, mx1 = -INFINITY;
#pragma unroll
            for (int nt = 0; nt < 8; nt++) {
                sacc[mt][nt][0] -= p2[nt].x; sacc[mt][nt][1] -= p2[nt].y;
                sacc[mt][nt][2] -= p2[nt].x; sacc[mt][nt][3] -= p2[nt].y;
                mx0 = fmaxf(mx0, fmaxf(sacc[mt][nt][0], sacc[mt][nt][1]));
                mx1 = fmaxf(mx1, fmaxf(sacc[mt][nt][2], sacc[mt][nt][3]));
            }
            mx0 = fmaxf(mx0, __shfl_xor_sync(0xFFFFFFFFu, mx0, 1));
            mx0 = fmaxf(mx0, __shfl_xor_sync(0xFFFFFFFFu, mx0, 2));
            mx1 = fmaxf(mx1, __shfl_xor_sync(0xFFFFFFFFu, mx1, 1));
            mx1 = fmaxf(mx1, __shfl_xor_sync(0xFFFFFFFFu, mx1, 2));

            const float mn0 = fmaxf(mrow[2 * mt], mx0);
            const float mn1 = fmaxf(mrow[2 * mt + 1], mx1);
            const float a0 = __expf(mrow[2 * mt] - mn0);
            const float a1 = __expf(mrow[2 * mt + 1] - mn1);
            float ls0 = 0.f, ls1 = 0.f;
#pragma unroll
            for (int nt = 0; nt < 8; nt++) {
                sacc[mt][nt][0] = __expf(sacc[mt][nt][0] - mn0);
                sacc[mt][nt][1] = __expf(sacc[mt][nt][1] - mn0);
                sacc[mt][nt][2] = __expf(sacc[mt][nt][2] - mn1);
                sacc[mt][nt][3] = __expf(sacc[mt][nt][3] - mn1);
                ls0 += sacc[mt][nt][0] + sacc[mt][nt][1];
                ls1 += sacc[mt][nt][2] + sacc[mt][nt][3];
            }
            ls0 += __shfl_xor_sync(0xFFFFFFFFu, ls0, 1);
            ls0 += __shfl_xor_sync(0xFFFFFFFFu, ls0, 2);
            ls1 += __shfl_xor_sync(0xFFFFFFFFu, ls1, 1);
            ls1 += __shfl_xor_sync(0xFFFFFFFFu, ls1, 2);
            lrow[2 * mt]     = lrow[2 * mt] * a0 + ls0;
            lrow[2 * mt + 1] = lrow[2 * mt + 1] * a1 + ls1;
            mrow[2 * mt] = mn0; mrow[2 * mt + 1] = mn1;
#pragma unroll
            for (int nt = 0; nt < 8; nt++) {
                oacc[mt][nt][0] *= a0; oacc[mt][nt][1] *= a0;
                oacc[mt][nt][2] *= a1; oacc[mt][nt][3] *= a1;
            }
        }

        // ---- PV: P single fp16 fragments from sacc (C layout == A layout)
#pragma unroll
        for (int kk = 0; kk < 4; kk++) {
            uint32_t ph[2][4];
#pragma unroll
            for (int mt = 0; mt < 2; mt++) {
                ph[mt][0] = pack16(sacc[mt][2 * kk][0],     sacc[mt][2 * kk][1]);
                ph[mt][1] = pack16(sacc[mt][2 * kk][2],     sacc[mt][2 * kk][3]);
                ph[mt][2] = pack16(sacc[mt][2 * kk + 1][0], sacc[mt][2 * kk + 1][1]);
                ph[mt][3] = pack16(sacc[mt][2 * kk + 1][2], sacc[mt][2 * kk + 1][3]);
            }
            const int cb2 = kk * 8 + tk;
#pragma unroll
            for (int nh = 0; nh < 2; nh++) {
                uint32_t vh[4][2];
#pragma unroll
                for (int j = 0; j < 4; j++) {
                    int nr = ((nh * 4 + j) * 8 + g) * RA + cb2;
                    vh[j][0] = Vs[nr];
                    vh[j][1] = Vs[nr + 4];
                }
#pragma unroll
                for (int j = 0; j < 4; j++)
#pragma unroll
                    for (int mt = 0; mt < 2; mt++)
                        mma16(oacc[mt][nh * 4 + j], ph[mt], vh[j]);
            }
        }
        __syncthreads();
    }

    // ---- epilogue: fp16 ctx for the output GEMM
#pragma unroll
    for (int mt = 0; mt < 2; mt++) {
        const float inv0 = 1.0f / lrow[2 * mt];
        const float inv1 = 1.0f / lrow[2 * mt + 1];
        size_t r0 = (size_t)(b * QLEN + q0 + wrow + mt * 16 + g) * RK;
        size_t r1 = (size_t)(b * QLEN + q0 + wrow + mt * 16 + g + 8) * RK;
#pragma unroll
        for (int nt = 0; nt < 8; nt++) {
            int d = nt * 8 + 2 * tk;
            int du = (h * HDIM + d) >> 1;
            g_Ch[r0 + du] = pack16(oacc[mt][nt][0] * inv0, oacc[mt][nt][1] * inv0);
            g_Ch[r1 + du] = pack16(oacc[mt][nt][2] * inv1, oacc[mt][nt][3] * inv1);
        }
    }
}

// ---------------------------------------------------------------------------
extern "C" void kernel_launch(void* const* d_in, const int* in_sizes, int n_in,
                              void* d_out, int out_size)
{
    (void)in_sizes; (void)n_in; (void)out_size;
    const float* query = (const float*)d_in[0];
    const float* key   = (const float*)d_in[1];
    const float* val   = (const float*)d_in[2];
    const int*   mask  = (const int*)  d_in[3];
    const float* Wq    = (const float*)d_in[4];
    const float* Wk    = (const float*)d_in[5];
    const float* Wv    = (const float*)d_in[6];
    const float* Wo    = (const float*)d_in[7];
    float* out = (float*)d_out;

    static int attrs_set = 0;
    if (!attrs_set) {
        cudaFuncSetAttribute(gemm_qkv,
                             cudaFuncAttributeMaxDynamicSharedMemorySize, GEMM_SMEM);
        cudaFuncSetAttribute(gemm_out,
                             cudaFuncAttributeMaxDynamicSharedMemorySize, GEMM_SMEM);
        cudaFuncSetAttribute(attn_tc,
                             cudaFuncAttributeMaxDynamicSharedMemorySize, ATT_SMEM);
        attrs_set = 1;
    }

    prep_split<<<2048, 256>>>(query, key, val, Wq, Wk, Wv, Wo, mask);

    dim3 gQKV(EMBED / 128, MROWS / 128, 3);     // (8, 32, 3)
    gemm_qkv<<<gQKV, 128, GEMM_SMEM>>>();

    dim3 gAttn(QLEN / 128, NHEAD, BATCH);       // (16, 16, 2)
    attn_tc<<<gAttn, 128, ATT_SMEM>>>();

    dim3 gOut(EMBED / 128, MROWS / 128);        // (8, 32)
    gemm_out<<<gOut, 128, GEMM_SMEM>>>(out);
}